// round 1
// baseline (speedup 1.0000x reference)
#include <cuda_runtime.h>
#include <math.h>

#define N_I 60000
#define N_E 30000
#define DI  128
#define DE  64
#define HH  64
#define E_II 960000
#define E_EI 480000
#define N_TRAIN 2048
#define N_CHOSEN 1024
#define F_INTERP 0.35f
#define F_SLOPE  0.2f

// ---------------- scratch (static device globals; no allocation) ----------------
__device__ __align__(16) float g_hs_ii[N_I * HH];
__device__ __align__(16) float g_hs_ei[N_E * HH];
__device__ __align__(16) float g_acc[N_I * HH];     // shared accumulator for o_ii + o_ei
__device__ __align__(16) float g_emb[N_I * HH];
__device__ float g_e_ii[E_II];
__device__ float g_e_ei[E_EI];
__device__ float g_sum_ii[N_I];
__device__ float g_sum_ei[N_I];
__device__ float g_s_ii[N_I];
__device__ float g_d_ii[N_I];
__device__ float g_d_ei[N_I];
__device__ float g_s_ei[N_E];
__device__ __align__(16) float g_ce[N_CHOSEN * HH];
__device__ float g_sq[N_CHOSEN];
__device__ int   g_nb[N_CHOSEN];
__device__ float g_wd_ii[DI];
__device__ float g_wd_ei[DI];

// ---------------- wd = Wdst @ adst (fold hd to a scalar per node) ----------------
__global__ void k_wd(const float* __restrict__ Wdst_ii, const float* __restrict__ adst_ii,
                     const float* __restrict__ Wdst_ei, const float* __restrict__ adst_ei) {
    int k = threadIdx.x;  // 128 threads, K = DI = 128
    float s0 = 0.f, s1 = 0.f;
    for (int c = 0; c < HH; c++) {
        s0 += Wdst_ii[k * HH + c] * adst_ii[c];
        s1 += Wdst_ei[k * HH + c] * adst_ei[c];
    }
    g_wd_ii[k] = s0;
    g_wd_ei[k] = s1;
}

// ---------------- fused GEMM: HS = A@W, S = HS@asrc, D = A@wd ----------------
// BM=64 rows/block, 128 threads, each thread 4 rows x 8 cols.
template <int K>
__global__ void k_gemm(const float* __restrict__ A, const float* __restrict__ W,
                       const float* __restrict__ asrc,
                       const float* __restrict__ wd0, const float* __restrict__ wd1,
                       float* __restrict__ HS, float* __restrict__ S,
                       float* __restrict__ D0, float* __restrict__ D1, int M) {
    extern __shared__ float sm[];
    float* As  = sm;                 // [K][65] transposed + padded
    float* Ws  = sm + K * 65;        // [K][64]
    float* asc = Ws + K * 64;        // [64]
    float* wds = asc + 64;           // [2*K] (only if wd0)

    const int tid  = threadIdx.x;
    const int row0 = blockIdx.x * 64;

    for (int idx = tid; idx < 64 * K; idx += 128) {
        int r = idx / K, k = idx % K;
        int row = row0 + r;
        As[k * 65 + r] = (row < M) ? A[row * K + k] : 0.f;
    }
    for (int idx = tid; idx < K * 64; idx += 128) Ws[idx] = W[idx];
    if (tid < 64) asc[tid] = asrc[tid];
    if (wd0) {
        for (int idx = tid; idx < K; idx += 128) {
            wds[idx]     = wd0[idx];
            wds[K + idx] = wd1[idx];
        }
    }
    __syncthreads();

    const int rg = tid >> 3;   // 0..15 (row group of 4)
    const int tx = tid & 7;    // 0..7  (col group of 8)
    float acc[4][8];
#pragma unroll
    for (int i = 0; i < 4; i++)
#pragma unroll
        for (int j = 0; j < 8; j++) acc[i][j] = 0.f;

    for (int k = 0; k < K; k++) {
        float4 b0 = *(const float4*)&Ws[k * 64 + tx * 8];
        float4 b1 = *(const float4*)&Ws[k * 64 + tx * 8 + 4];
#pragma unroll
        for (int i = 0; i < 4; i++) {
            float a = As[k * 65 + rg * 4 + i];
            acc[i][0] += a * b0.x; acc[i][1] += a * b0.y;
            acc[i][2] += a * b0.z; acc[i][3] += a * b0.w;
            acc[i][4] += a * b1.x; acc[i][5] += a * b1.y;
            acc[i][6] += a * b1.z; acc[i][7] += a * b1.w;
        }
    }

    float a0 = asc[tx * 8 + 0], a1 = asc[tx * 8 + 1], a2 = asc[tx * 8 + 2], a3 = asc[tx * 8 + 3];
    float a4 = asc[tx * 8 + 4], a5 = asc[tx * 8 + 5], a6 = asc[tx * 8 + 6], a7 = asc[tx * 8 + 7];
#pragma unroll
    for (int i = 0; i < 4; i++) {
        int row = row0 + rg * 4 + i;
        float s = acc[i][0] * a0 + acc[i][1] * a1 + acc[i][2] * a2 + acc[i][3] * a3 +
                  acc[i][4] * a4 + acc[i][5] * a5 + acc[i][6] * a6 + acc[i][7] * a7;
        s += __shfl_down_sync(0xffffffffu, s, 4, 8);
        s += __shfl_down_sync(0xffffffffu, s, 2, 8);
        s += __shfl_down_sync(0xffffffffu, s, 1, 8);
        if (row < M) {
            *(float4*)&HS[row * 64 + tx * 8]     = make_float4(acc[i][0], acc[i][1], acc[i][2], acc[i][3]);
            *(float4*)&HS[row * 64 + tx * 8 + 4] = make_float4(acc[i][4], acc[i][5], acc[i][6], acc[i][7]);
            if (tx == 0) S[row] = s;
        }
    }

    if (wd0 && tid < 64) {
        int row = row0 + tid;
        if (row < M) {
            float d0 = 0.f, d1 = 0.f;
            for (int k = 0; k < K; k++) {
                float a = As[k * 65 + tid];
                d0 += a * wds[k];
                d1 += a * wds[K + k];
            }
            D0[row] = d0;
            D1[row] = d1;
        }
    }
}

// ---------------- edge pass 1: e = exp(leaky(s[src]+d[dst])); sum per dst ----------------
__global__ void k_edge1(const int* __restrict__ src, const int* __restrict__ dst,
                        const float* __restrict__ S, const float* __restrict__ D,
                        float* __restrict__ earr, float* __restrict__ sum, int E) {
    int e = blockIdx.x * blockDim.x + threadIdx.x;
    if (e >= E) return;
    float a = __ldg(&S[src[e]]) + __ldg(&D[dst[e]]);
    a = a > 0.f ? a : F_SLOPE * a;
    float ee = expf(a);
    earr[e] = ee;
    atomicAdd(&sum[dst[e]], ee);
}

// ---------------- edge pass 2: acc[dst] += (e/sum[dst]) * hs[src]  (16 lanes/edge, v4 red) --
__global__ void k_edge2(const int* __restrict__ src, const int* __restrict__ dst,
                        const float* __restrict__ earr, const float* __restrict__ sum,
                        const float* __restrict__ HS, float* __restrict__ acc, int E) {
    int g = blockIdx.x * blockDim.x + threadIdx.x;
    int e = g >> 4;
    int l = g & 15;
    if (e >= E) return;
    int s = src[e], d = dst[e];
    float w = earr[e] / sum[d];
    float4 h = *(const float4*)&HS[s * 64 + l * 4];
    float* p = &acc[d * 64 + l * 4];
    asm volatile("red.global.add.v4.f32 [%0], {%1,%2,%3,%4};"
                 :: "l"(__cvta_generic_to_global(p)),
                    "f"(w * h.x), "f"(w * h.y), "f"(w * h.z), "f"(w * h.w)
                 : "memory");
}

// ---------------- emb = relu(0.5*(acc + b_ii + b_ei)) ----------------
__global__ void k_combine(const float* __restrict__ b_ii, const float* __restrict__ b_ei) {
    int i = blockIdx.x * blockDim.x + threadIdx.x;
    if (i >= N_I * HH) return;
    int c = i & 63;
    float v = 0.5f * (g_acc[i] + __ldg(&b_ii[c]) + __ldg(&b_ei[c]));
    g_emb[i] = v > 0.f ? v : 0.f;
}

// ---------------- gather chosen embeddings + squared norms ----------------
__global__ void k_ce(const int* __restrict__ chosen) {
    int i = blockIdx.x * (blockDim.x >> 5) + (threadIdx.x >> 5);
    int lane = threadIdx.x & 31;
    if (i >= N_CHOSEN) return;
    int n = chosen[i];
    float v0 = g_emb[n * 64 + lane];
    float v1 = g_emb[n * 64 + 32 + lane];
    g_ce[i * 64 + lane]      = v0;
    g_ce[i * 64 + 32 + lane] = v1;
    float sq = v0 * v0 + v1 * v1;
    for (int off = 16; off; off >>= 1) sq += __shfl_down_sync(0xffffffffu, sq, off);
    if (lane == 0) g_sq[i] = sq;
}

// ---------------- nearest neighbor among chosen (argmin, first-index tiebreak) --------------
__global__ void k_nn() {
    int i = blockIdx.x;
    __shared__ float cei[64];
    __shared__ float bd[256];
    __shared__ int   bj[256];
    int tid = threadIdx.x;
    if (tid < 64) cei[tid] = g_ce[i * 64 + tid];
    __syncthreads();
    float sqi = g_sq[i];
    float best = 3.4e38f;
    int bestj = 0x7fffffff;
    for (int j = tid; j < N_CHOSEN; j += 256) {
        if (j == i) continue;
        float dot = 0.f;
#pragma unroll 16
        for (int k = 0; k < 64; k++) dot += cei[k] * g_ce[j * 64 + k];
        float d2 = sqi + g_sq[j] - 2.f * dot;
        d2 = d2 > 0.f ? d2 : 0.f;
        if (d2 < best || (d2 == best && j < bestj)) { best = d2; bestj = j; }
    }
    bd[tid] = best; bj[tid] = bestj;
    __syncthreads();
    for (int s = 128; s; s >>= 1) {
        if (tid < s) {
            if (bd[tid + s] < bd[tid] || (bd[tid + s] == bd[tid] && bj[tid + s] < bj[tid])) {
                bd[tid] = bd[tid + s]; bj[tid] = bj[tid + s];
            }
        }
        __syncthreads();
    }
    if (tid == 0) g_nb[i] = bj[0];
}

// ---------------- classifier head + softmax + extra output sections ----------------
__global__ void k_final(const float* __restrict__ linW, const float* __restrict__ linb,
                        const float* __restrict__ rn, const int* __restrict__ labels,
                        const int* __restrict__ chosen,
                        float* __restrict__ out, int probN, int writeExtras) {
    int n = blockIdx.x * (blockDim.x >> 5) + (threadIdx.x >> 5);
    int lane = threadIdx.x & 31;
    if (n >= probN) return;
    float v0, v1;
    if (n < N_I) {
        v0 = g_emb[n * 64 + lane];
        v1 = g_emb[n * 64 + 32 + lane];
    } else {
        int i = n - N_I;
        int nbi = g_nb[i];
        float c0 = g_ce[i * 64 + lane],      c1 = g_ce[i * 64 + 32 + lane];
        float n0 = g_ce[nbi * 64 + lane],    n1 = g_ce[nbi * 64 + 32 + lane];
        v0 = c0 + (n0 - c0) * F_INTERP;
        v1 = c1 + (n1 - c1) * F_INTERP;
    }
    float l0 = v0 * __ldg(&linW[lane * 2])            + v1 * __ldg(&linW[(lane + 32) * 2]);
    float l1 = v0 * __ldg(&linW[lane * 2 + 1])        + v1 * __ldg(&linW[(lane + 32) * 2 + 1]);
    for (int off = 16; off; off >>= 1) {
        l0 += __shfl_down_sync(0xffffffffu, l0, off);
        l1 += __shfl_down_sync(0xffffffffu, l1, off);
    }
    if (lane == 0) {
        l0 += __ldg(&linb[0]);
        l1 += __ldg(&linb[1]);
        float m = fmaxf(l0, l1);
        float e0 = expf(l0 - m), e1 = expf(l1 - m);
        float inv = 1.f / (e0 + e1);
        out[n * 2]     = e0 * inv;
        out[n * 2 + 1] = e1 * inv;
        if (writeExtras) {
            int moff = probN * 2;
            out[moff + n]             = (n >= N_I) ? 1.f : 0.f;             // train_mask (idx_train set later)
            out[moff + probN + n]     = (n < N_I) ? (float)labels[n] : 1.f; // labels_all
            float r;
            if (n < N_I) r = rn[n];
            else {
                int i = n - N_I;
                float rc = rn[chosen[i]];
                r = rc + (rn[chosen[g_nb[i]]] - rc) * F_INTERP;
            }
            out[moff + 2 * probN + n] = r;                                   // rn_all
        }
    }
}

__global__ void k_mask(const int* __restrict__ idx_train, float* __restrict__ out, int moff) {
    int t = blockIdx.x * blockDim.x + threadIdx.x;
    if (t < N_TRAIN) out[moff + idx_train[t]] = 1.f;
}

// ---------------- launch ----------------
extern "C" void kernel_launch(void* const* d_in, const int* in_sizes, int n_in,
                              void* d_out, int out_size) {
    const float* x_i     = (const float*)d_in[0];
    const float* x_e     = (const float*)d_in[1];
    const float* Wsrc_ii = (const float*)d_in[2];
    const float* Wdst_ii = (const float*)d_in[3];
    const float* asrc_ii = (const float*)d_in[4];
    const float* adst_ii = (const float*)d_in[5];
    const float* b_ii    = (const float*)d_in[6];
    // d_in[7..11]: ie branch — computed by reference but unused downstream; skipped.
    const float* Wsrc_ei = (const float*)d_in[12];
    const float* Wdst_ei = (const float*)d_in[13];
    const float* asrc_ei = (const float*)d_in[14];
    const float* adst_ei = (const float*)d_in[15];
    const float* b_ei    = (const float*)d_in[16];
    const float* linW    = (const float*)d_in[17];
    const float* linb    = (const float*)d_in[18];
    const float* rn      = (const float*)d_in[19];
    const int*   eii     = (const int*)d_in[20];
    const int*   eei     = (const int*)d_in[22];
    const int*   labels  = (const int*)d_in[23];
    const int*   idxtr   = (const int*)d_in[24];
    const int*   chosen  = (const int*)d_in[25];
    float* out = (float*)d_out;

    // scratch symbol addresses
    void *p_acc, *p_sum_ii, *p_sum_ei;
    void *p_hs_ii, *p_hs_ei, *p_s_ii, *p_d_ii, *p_d_ei, *p_s_ei;
    void *p_wd_ii, *p_wd_ei, *p_e_ii, *p_e_ei;
    cudaGetSymbolAddress(&p_acc, g_acc);
    cudaGetSymbolAddress(&p_sum_ii, g_sum_ii);
    cudaGetSymbolAddress(&p_sum_ei, g_sum_ei);
    cudaGetSymbolAddress(&p_hs_ii, g_hs_ii);
    cudaGetSymbolAddress(&p_hs_ei, g_hs_ei);
    cudaGetSymbolAddress(&p_s_ii, g_s_ii);
    cudaGetSymbolAddress(&p_d_ii, g_d_ii);
    cudaGetSymbolAddress(&p_d_ei, g_d_ei);
    cudaGetSymbolAddress(&p_s_ei, g_s_ei);
    cudaGetSymbolAddress(&p_wd_ii, g_wd_ii);
    cudaGetSymbolAddress(&p_wd_ei, g_wd_ei);
    cudaGetSymbolAddress(&p_e_ii, g_e_ii);
    cudaGetSymbolAddress(&p_e_ei, g_e_ei);

    cudaMemsetAsync(p_acc, 0, (size_t)N_I * HH * sizeof(float));
    cudaMemsetAsync(p_sum_ii, 0, (size_t)N_I * sizeof(float));
    cudaMemsetAsync(p_sum_ei, 0, (size_t)N_I * sizeof(float));

    k_wd<<<1, 128>>>(Wdst_ii, adst_ii, Wdst_ei, adst_ei);

    size_t sm128 = (size_t)(128 * 65 + 128 * 64 + 64 + 2 * 128) * sizeof(float);  // 67328 B
    size_t sm64  = (size_t)(64 * 65 + 64 * 64 + 64) * sizeof(float);
    cudaFuncSetAttribute(k_gemm<128>, cudaFuncAttributeMaxDynamicSharedMemorySize, 69632);
    cudaFuncSetAttribute(k_gemm<64>,  cudaFuncAttributeMaxDynamicSharedMemorySize, 49152);

    k_gemm<128><<<(N_I + 63) / 64, 128, sm128>>>(
        x_i, Wsrc_ii, asrc_ii, (const float*)p_wd_ii, (const float*)p_wd_ei,
        (float*)p_hs_ii, (float*)p_s_ii, (float*)p_d_ii, (float*)p_d_ei, N_I);
    k_gemm<64><<<(N_E + 63) / 64, 128, sm64>>>(
        x_e, Wsrc_ei, asrc_ei, nullptr, nullptr,
        (float*)p_hs_ei, (float*)p_s_ei, nullptr, nullptr, N_E);

    k_edge1<<<(E_II + 255) / 256, 256>>>(eii, eii + E_II, (const float*)p_s_ii,
                                         (const float*)p_d_ii, (float*)p_e_ii,
                                         (float*)p_sum_ii, E_II);
    k_edge1<<<(E_EI + 255) / 256, 256>>>(eei, eei + E_EI, (const float*)p_s_ei,
                                         (const float*)p_d_ei, (float*)p_e_ei,
                                         (float*)p_sum_ei, E_EI);

    k_edge2<<<(E_II * 16 + 255) / 256, 256>>>(eii, eii + E_II, (const float*)p_e_ii,
                                              (const float*)p_sum_ii, (const float*)p_hs_ii,
                                              (float*)p_acc, E_II);
    k_edge2<<<(E_EI * 16 + 255) / 256, 256>>>(eei, eei + E_EI, (const float*)p_e_ei,
                                              (const float*)p_sum_ei, (const float*)p_hs_ei,
                                              (float*)p_acc, E_EI);

    k_combine<<<(N_I * HH + 255) / 256, 256>>>(b_ii, b_ei);

    k_ce<<<(N_CHOSEN + 7) / 8, 256>>>(chosen);
    k_nn<<<N_CHOSEN, 256>>>();

    int probN = N_I + N_CHOSEN;  // 61024
    int writeExtras = (out_size >= probN * 5) ? 1 : 0;
    k_final<<<(probN + 7) / 8, 256>>>(linW, linb, rn, labels, chosen, out, probN, writeExtras);
    if (writeExtras) k_mask<<<(N_TRAIN + 255) / 256, 256>>>(idxtr, out, probN * 2);
}

// round 2
// speedup vs baseline: 1.2054x; 1.2054x over previous
#include <cuda_runtime.h>
#include <math.h>

#define N_I 60000
#define N_E 30000
#define DI  128
#define DE  64
#define HH  64
#define E_II 960000
#define E_EI 480000
#define N_TRAIN 2048
#define N_CHOSEN 1024
#define F_INTERP 0.35f
#define F_SLOPE  0.2f
#define CAP_II 64
#define CAP_EI 48

// ---------------- scratch (static device globals; no allocation) ----------------
__device__ __align__(16) float g_hs_ii[N_I * HH];
__device__ __align__(16) float g_hs_ei[N_E * HH];
__device__ __align__(16) float g_emb[N_I * HH];
__device__ float g_s_ii[N_I];
__device__ float g_d_ii[N_I];
__device__ float g_d_ei[N_I];
__device__ float g_s_ei[N_E];
__device__ int   g_deg_ii[N_I];
__device__ int   g_deg_ei[N_I];
__device__ int   g_bkt_ii[(size_t)N_I * CAP_II];
__device__ int   g_bkt_ei[(size_t)N_I * CAP_EI];
__device__ __align__(16) float g_ce[N_CHOSEN * HH];
__device__ float g_sq[N_CHOSEN];
__device__ int   g_nb[N_CHOSEN];
__device__ float g_wd_ii[DI];
__device__ float g_wd_ei[DI];

// ---------------- wd = Wdst @ adst (fold hd to a scalar per node) ----------------
__global__ void k_wd(const float* __restrict__ Wdst_ii, const float* __restrict__ adst_ii,
                     const float* __restrict__ Wdst_ei, const float* __restrict__ adst_ei) {
    int k = threadIdx.x;  // 128 threads
    float s0 = 0.f, s1 = 0.f;
    for (int c = 0; c < HH; c++) {
        s0 += Wdst_ii[k * HH + c] * adst_ii[c];
        s1 += Wdst_ei[k * HH + c] * adst_ei[c];
    }
    g_wd_ii[k] = s0;
    g_wd_ei[k] = s1;
}

// ---------------- fused GEMM: HS = A@W, S = HS@asrc, D = A@wd ----------------
template <int K>
__global__ void k_gemm(const float* __restrict__ A, const float* __restrict__ W,
                       const float* __restrict__ asrc,
                       const float* __restrict__ wd0, const float* __restrict__ wd1,
                       float* __restrict__ HS, float* __restrict__ S,
                       float* __restrict__ D0, float* __restrict__ D1, int M) {
    extern __shared__ float sm[];
    float* As  = sm;                 // [K][65]
    float* Ws  = sm + K * 65;        // [K][64]
    float* asc = Ws + K * 64;        // [64]
    float* wds = asc + 64;           // [2*K]

    const int tid  = threadIdx.x;
    const int row0 = blockIdx.x * 64;

    for (int idx = tid; idx < 64 * K; idx += 128) {
        int r = idx / K, k = idx % K;
        int row = row0 + r;
        As[k * 65 + r] = (row < M) ? A[row * K + k] : 0.f;
    }
    for (int idx = tid; idx < K * 64; idx += 128) Ws[idx] = W[idx];
    if (tid < 64) asc[tid] = asrc[tid];
    if (wd0) {
        for (int idx = tid; idx < K; idx += 128) {
            wds[idx]     = wd0[idx];
            wds[K + idx] = wd1[idx];
        }
    }
    __syncthreads();

    const int rg = tid >> 3;
    const int tx = tid & 7;
    float acc[4][8];
#pragma unroll
    for (int i = 0; i < 4; i++)
#pragma unroll
        for (int j = 0; j < 8; j++) acc[i][j] = 0.f;

    for (int k = 0; k < K; k++) {
        float4 b0 = *(const float4*)&Ws[k * 64 + tx * 8];
        float4 b1 = *(const float4*)&Ws[k * 64 + tx * 8 + 4];
#pragma unroll
        for (int i = 0; i < 4; i++) {
            float a = As[k * 65 + rg * 4 + i];
            acc[i][0] += a * b0.x; acc[i][1] += a * b0.y;
            acc[i][2] += a * b0.z; acc[i][3] += a * b0.w;
            acc[i][4] += a * b1.x; acc[i][5] += a * b1.y;
            acc[i][6] += a * b1.z; acc[i][7] += a * b1.w;
        }
    }

    float a0 = asc[tx * 8 + 0], a1 = asc[tx * 8 + 1], a2 = asc[tx * 8 + 2], a3 = asc[tx * 8 + 3];
    float a4 = asc[tx * 8 + 4], a5 = asc[tx * 8 + 5], a6 = asc[tx * 8 + 6], a7 = asc[tx * 8 + 7];
#pragma unroll
    for (int i = 0; i < 4; i++) {
        int row = row0 + rg * 4 + i;
        float s = acc[i][0] * a0 + acc[i][1] * a1 + acc[i][2] * a2 + acc[i][3] * a3 +
                  acc[i][4] * a4 + acc[i][5] * a5 + acc[i][6] * a6 + acc[i][7] * a7;
        s += __shfl_down_sync(0xffffffffu, s, 4, 8);
        s += __shfl_down_sync(0xffffffffu, s, 2, 8);
        s += __shfl_down_sync(0xffffffffu, s, 1, 8);
        if (row < M) {
            *(float4*)&HS[row * 64 + tx * 8]     = make_float4(acc[i][0], acc[i][1], acc[i][2], acc[i][3]);
            *(float4*)&HS[row * 64 + tx * 8 + 4] = make_float4(acc[i][4], acc[i][5], acc[i][6], acc[i][7]);
            if (tx == 0) S[row] = s;
        }
    }

    if (wd0 && tid < 64) {
        int row = row0 + tid;
        if (row < M) {
            float d0 = 0.f, d1 = 0.f;
            for (int k = 0; k < K; k++) {
                float a = As[k * 65 + tid];
                d0 += a * wds[k];
                d1 += a * wds[K + k];
            }
            D0[row] = d0;
            D1[row] = d1;
        }
    }
}

// ---------------- bucket scatter: per-dst incoming edge lists ----------------
__global__ void k_scatter(const int* __restrict__ src, const int* __restrict__ dst,
                          int* __restrict__ deg, int* __restrict__ bkt, int E, int cap) {
    int e = blockIdx.x * blockDim.x + threadIdx.x;
    if (e >= E) return;
    int d = dst[e];
    int pos = atomicAdd(&deg[d], 1);
    if (pos < cap) bkt[(size_t)d * cap + pos] = src[e];
}

// ---------------- per-graph gather-aggregate (warp-level helper) ----------------
__device__ __forceinline__ void aggr_one(const int* __restrict__ bkt, int deg,
                                         const float* __restrict__ S, float dval,
                                         const float* __restrict__ HS,
                                         int lane, float2* res) {
    float vx = 0.f, vy = 0.f, esum = 0.f;
    for (int base = 0; base < deg; base += 32) {
        int j = base + lane;
        int sidx = 0;
        float e = 0.f;
        if (j < deg) {
            sidx = bkt[j];
            float a = __ldg(&S[sidx]) + dval;
            a = a > 0.f ? a : F_SLOPE * a;
            e = expf(a);
        }
        int cnt = min(32, deg - base);
#pragma unroll 4
        for (int t = 0; t < cnt; t++) {
            float et = __shfl_sync(0xffffffffu, e, t);
            int   st = __shfl_sync(0xffffffffu, sidx, t);
            float2 h = *(const float2*)&HS[st * 64 + lane * 2];
            vx += et * h.x;
            vy += et * h.y;
        }
        esum += e;
    }
#pragma unroll
    for (int off = 16; off; off >>= 1)
        esum += __shfl_xor_sync(0xffffffffu, esum, off);
    if (esum > 0.f) {
        float inv = 1.f / esum;
        res->x += vx * inv;
        res->y += vy * inv;
    }
}

// ---------------- fused aggregation for both graphs + bias + relu -> emb ----------------
__global__ void k_aggr(const float* __restrict__ b_ii, const float* __restrict__ b_ei) {
    int dst = blockIdx.x * (blockDim.x >> 5) + (threadIdx.x >> 5);
    int lane = threadIdx.x & 31;
    if (dst >= N_I) return;

    float2 res = make_float2(0.f, 0.f);
    int deg0 = min(g_deg_ii[dst], CAP_II);
    int deg1 = min(g_deg_ei[dst], CAP_EI);
    aggr_one(&g_bkt_ii[(size_t)dst * CAP_II], deg0, g_s_ii, g_d_ii[dst], g_hs_ii, lane, &res);
    aggr_one(&g_bkt_ei[(size_t)dst * CAP_EI], deg1, g_s_ei, g_d_ei[dst], g_hs_ei, lane, &res);

    int c0 = lane * 2;
    float v0 = 0.5f * (res.x + __ldg(&b_ii[c0])     + __ldg(&b_ei[c0]));
    float v1 = 0.5f * (res.y + __ldg(&b_ii[c0 + 1]) + __ldg(&b_ei[c0 + 1]));
    float2 o;
    o.x = v0 > 0.f ? v0 : 0.f;
    o.y = v1 > 0.f ? v1 : 0.f;
    *(float2*)&g_emb[dst * 64 + c0] = o;
}

// ---------------- gather chosen embeddings + squared norms ----------------
__global__ void k_ce(const int* __restrict__ chosen) {
    int i = blockIdx.x * (blockDim.x >> 5) + (threadIdx.x >> 5);
    int lane = threadIdx.x & 31;
    if (i >= N_CHOSEN) return;
    int n = chosen[i];
    float v0 = g_emb[n * 64 + lane];
    float v1 = g_emb[n * 64 + 32 + lane];
    g_ce[i * 64 + lane]      = v0;
    g_ce[i * 64 + 32 + lane] = v1;
    float sq = v0 * v0 + v1 * v1;
    for (int off = 16; off; off >>= 1) sq += __shfl_down_sync(0xffffffffu, sq, off);
    if (lane == 0) g_sq[i] = sq;
}

// ---------------- tiled nearest neighbor: 8 i's per block share j-tiles ----------------
__global__ void k_nn2() {
    __shared__ float tile[64 * 65];
    __shared__ float sqj[64];
    __shared__ float cei[8 * 64];
    int tid = threadIdx.x;
    int wid = tid >> 5, lane = tid & 31;
    int i = blockIdx.x * 8 + wid;

    cei[wid * 64 + lane]      = g_ce[i * 64 + lane];
    cei[wid * 64 + 32 + lane] = g_ce[i * 64 + 32 + lane];
    float sqi = g_sq[i];
    float best = 3.4e38f;
    int bestj = 0x7fffffff;

    for (int tb = 0; tb < N_CHOSEN; tb += 64) {
        __syncthreads();
        for (int idx = tid; idx < 64 * 64; idx += 256) {
            int j = idx >> 6, k = idx & 63;
            tile[j * 65 + k] = g_ce[(tb + j) * 64 + k];
        }
        if (tid < 64) sqj[tid] = g_sq[tb + tid];
        __syncthreads();

#pragma unroll
        for (int half = 0; half < 2; half++) {
            int jl = lane + half * 32;
            int j = tb + jl;
            if (j == i) continue;
            float dot = 0.f;
#pragma unroll 16
            for (int k = 0; k < 64; k++) dot += cei[wid * 64 + k] * tile[jl * 65 + k];
            float d2 = sqi + sqj[jl] - 2.f * dot;
            d2 = d2 > 0.f ? d2 : 0.f;
            if (d2 < best || (d2 == best && j < bestj)) { best = d2; bestj = j; }
        }
    }
#pragma unroll
    for (int off = 16; off; off >>= 1) {
        float ob = __shfl_down_sync(0xffffffffu, best, off);
        int   oj = __shfl_down_sync(0xffffffffu, bestj, off);
        if (ob < best || (ob == best && oj < bestj)) { best = ob; bestj = oj; }
    }
    if (lane == 0) g_nb[i] = bestj;
}

// ---------------- classifier head + softmax + extra output sections ----------------
__global__ void k_final(const float* __restrict__ linW, const float* __restrict__ linb,
                        const float* __restrict__ rn, const int* __restrict__ labels,
                        const int* __restrict__ chosen,
                        float* __restrict__ out, int probN, int writeExtras) {
    int n = blockIdx.x * (blockDim.x >> 5) + (threadIdx.x >> 5);
    int lane = threadIdx.x & 31;
    if (n >= probN) return;
    float v0, v1;
    if (n < N_I) {
        v0 = g_emb[n * 64 + lane];
        v1 = g_emb[n * 64 + 32 + lane];
    } else {
        int i = n - N_I;
        int nbi = g_nb[i];
        float c0 = g_ce[i * 64 + lane],   c1 = g_ce[i * 64 + 32 + lane];
        float n0 = g_ce[nbi * 64 + lane], n1 = g_ce[nbi * 64 + 32 + lane];
        v0 = c0 + (n0 - c0) * F_INTERP;
        v1 = c1 + (n1 - c1) * F_INTERP;
    }
    float l0 = v0 * __ldg(&linW[lane * 2])     + v1 * __ldg(&linW[(lane + 32) * 2]);
    float l1 = v0 * __ldg(&linW[lane * 2 + 1]) + v1 * __ldg(&linW[(lane + 32) * 2 + 1]);
    for (int off = 16; off; off >>= 1) {
        l0 += __shfl_down_sync(0xffffffffu, l0, off);
        l1 += __shfl_down_sync(0xffffffffu, l1, off);
    }
    if (lane == 0) {
        l0 += __ldg(&linb[0]);
        l1 += __ldg(&linb[1]);
        float m = fmaxf(l0, l1);
        float e0 = expf(l0 - m), e1 = expf(l1 - m);
        float inv = 1.f / (e0 + e1);
        out[n * 2]     = e0 * inv;
        out[n * 2 + 1] = e1 * inv;
        if (writeExtras) {
            int moff = probN * 2;
            out[moff + n]         = (n >= N_I) ? 1.f : 0.f;
            out[moff + probN + n] = (n < N_I) ? (float)labels[n] : 1.f;
            float r;
            if (n < N_I) r = rn[n];
            else {
                int i = n - N_I;
                float rc = rn[chosen[i]];
                r = rc + (rn[chosen[g_nb[i]]] - rc) * F_INTERP;
            }
            out[moff + 2 * probN + n] = r;
        }
    }
}

__global__ void k_mask(const int* __restrict__ idx_train, float* __restrict__ out, int moff) {
    int t = blockIdx.x * blockDim.x + threadIdx.x;
    if (t < N_TRAIN) out[moff + idx_train[t]] = 1.f;
}

// ---------------- launch ----------------
extern "C" void kernel_launch(void* const* d_in, const int* in_sizes, int n_in,
                              void* d_out, int out_size) {
    const float* x_i     = (const float*)d_in[0];
    const float* x_e     = (const float*)d_in[1];
    const float* Wsrc_ii = (const float*)d_in[2];
    const float* Wdst_ii = (const float*)d_in[3];
    const float* asrc_ii = (const float*)d_in[4];
    const float* adst_ii = (const float*)d_in[5];
    const float* b_ii    = (const float*)d_in[6];
    // d_in[7..11]: ie branch — unused downstream in the reference; skipped.
    const float* Wsrc_ei = (const float*)d_in[12];
    const float* Wdst_ei = (const float*)d_in[13];
    const float* asrc_ei = (const float*)d_in[14];
    const float* adst_ei = (const float*)d_in[15];
    const float* b_ei    = (const float*)d_in[16];
    const float* linW    = (const float*)d_in[17];
    const float* linb    = (const float*)d_in[18];
    const float* rn      = (const float*)d_in[19];
    const int*   eii     = (const int*)d_in[20];
    const int*   eei     = (const int*)d_in[22];
    const int*   labels  = (const int*)d_in[23];
    const int*   idxtr   = (const int*)d_in[24];
    const int*   chosen  = (const int*)d_in[25];
    float* out = (float*)d_out;

    void *p_hs_ii, *p_hs_ei, *p_s_ii, *p_d_ii, *p_d_ei, *p_s_ei;
    void *p_wd_ii, *p_wd_ei, *p_deg_ii, *p_deg_ei, *p_bkt_ii, *p_bkt_ei;
    cudaGetSymbolAddress(&p_hs_ii, g_hs_ii);
    cudaGetSymbolAddress(&p_hs_ei, g_hs_ei);
    cudaGetSymbolAddress(&p_s_ii, g_s_ii);
    cudaGetSymbolAddress(&p_d_ii, g_d_ii);
    cudaGetSymbolAddress(&p_d_ei, g_d_ei);
    cudaGetSymbolAddress(&p_s_ei, g_s_ei);
    cudaGetSymbolAddress(&p_wd_ii, g_wd_ii);
    cudaGetSymbolAddress(&p_wd_ei, g_wd_ei);
    cudaGetSymbolAddress(&p_deg_ii, g_deg_ii);
    cudaGetSymbolAddress(&p_deg_ei, g_deg_ei);
    cudaGetSymbolAddress(&p_bkt_ii, g_bkt_ii);
    cudaGetSymbolAddress(&p_bkt_ei, g_bkt_ei);

    cudaMemsetAsync(p_deg_ii, 0, (size_t)N_I * sizeof(int));
    cudaMemsetAsync(p_deg_ei, 0, (size_t)N_I * sizeof(int));

    k_wd<<<1, 128>>>(Wdst_ii, adst_ii, Wdst_ei, adst_ei);

    size_t sm128 = (size_t)(128 * 65 + 128 * 64 + 64 + 2 * 128) * sizeof(float);
    size_t sm64  = (size_t)(64 * 65 + 64 * 64 + 64) * sizeof(float);
    cudaFuncSetAttribute(k_gemm<128>, cudaFuncAttributeMaxDynamicSharedMemorySize, 69632);
    cudaFuncSetAttribute(k_gemm<64>,  cudaFuncAttributeMaxDynamicSharedMemorySize, 49152);

    // bucket builds run concurrently with GEMMs (independent)
    k_scatter<<<(E_II + 255) / 256, 256>>>(eii, eii + E_II, (int*)p_deg_ii, (int*)p_bkt_ii, E_II, CAP_II);
    k_scatter<<<(E_EI + 255) / 256, 256>>>(eei, eei + E_EI, (int*)p_deg_ei, (int*)p_bkt_ei, E_EI, CAP_EI);

    k_gemm<128><<<(N_I + 63) / 64, 128, sm128>>>(
        x_i, Wsrc_ii, asrc_ii, (const float*)p_wd_ii, (const float*)p_wd_ei,
        (float*)p_hs_ii, (float*)p_s_ii, (float*)p_d_ii, (float*)p_d_ei, N_I);
    k_gemm<64><<<(N_E + 63) / 64, 128, sm64>>>(
        x_e, Wsrc_ei, asrc_ei, nullptr, nullptr,
        (float*)p_hs_ei, (float*)p_s_ei, nullptr, nullptr, N_E);

    k_aggr<<<(N_I + 7) / 8, 256>>>(b_ii, b_ei);

    k_ce<<<(N_CHOSEN + 7) / 8, 256>>>(chosen);
    k_nn2<<<N_CHOSEN / 8, 256>>>();

    int probN = N_I + N_CHOSEN;
    int writeExtras = (out_size >= probN * 5) ? 1 : 0;
    k_final<<<(probN + 7) / 8, 256>>>(linW, linb, rn, labels, chosen, out, probN, writeExtras);
    if (writeExtras) k_mask<<<(N_TRAIN + 255) / 256, 256>>>(idxtr, out, probN * 2);
}

// round 3
// speedup vs baseline: 1.3330x; 1.1058x over previous
#include <cuda_runtime.h>
#include <math.h>

#define N_I 60000
#define N_E 30000
#define DI  128
#define DE  64
#define HH  64
#define E_II 960000
#define E_EI 480000
#define N_TRAIN 2048
#define N_CHOSEN 1024
#define F_INTERP 0.35f
#define F_SLOPE  0.2f
#define CAP_II 64
#define CAP_EI 48

// ---------------- scratch (static device globals; no allocation) ----------------
__device__ __align__(16) float g_hs_ii[N_I * HH];
__device__ __align__(16) float g_hs_ei[N_E * HH];
__device__ __align__(16) float g_emb[N_I * HH];
__device__ float g_s_ii[N_I];
__device__ float g_d_ii[N_I];
__device__ float g_d_ei[N_I];
__device__ float g_s_ei[N_E];
__device__ int   g_deg_ii[N_I];
__device__ int   g_deg_ei[N_I];
__device__ int   g_bkt_ii[(size_t)N_I * CAP_II];
__device__ int   g_bkt_ei[(size_t)N_I * CAP_EI];
__device__ __align__(16) float g_ce[N_CHOSEN * HH];
__device__ float g_sq[N_CHOSEN];
__device__ int   g_nb[N_CHOSEN];
__device__ float g_wd_ii[DI];
__device__ float g_wd_ei[DI];

// ---------------- packed f32x2 helpers (Blackwell FFMA2) ----------------
__device__ __forceinline__ unsigned long long pk2(float x) {
    unsigned long long r;
    asm("mov.b64 %0, {%1, %1};" : "=l"(r) : "f"(x));
    return r;
}
__device__ __forceinline__ void fma2(unsigned long long& d, unsigned long long a,
                                     unsigned long long b) {
    asm("fma.rn.f32x2 %0, %1, %2, %0;" : "+l"(d) : "l"(a), "l"(b));
}
__device__ __forceinline__ void upk(unsigned long long v, float& lo, float& hi) {
    asm("mov.b64 {%0, %1}, %2;" : "=f"(lo), "=f"(hi) : "l"(v));
}

// ---------------- wd = Wdst @ adst (fold hd to a scalar per node) ----------------
__global__ void k_wd(const float* __restrict__ Wdst_ii, const float* __restrict__ adst_ii,
                     const float* __restrict__ Wdst_ei, const float* __restrict__ adst_ei) {
    int k = threadIdx.x;  // 128 threads
    float s0 = 0.f, s1 = 0.f;
    for (int c = 0; c < HH; c++) {
        s0 += Wdst_ii[k * HH + c] * adst_ii[c];
        s1 += Wdst_ei[k * HH + c] * adst_ei[c];
    }
    g_wd_ii[k] = s0;
    g_wd_ei[k] = s1;
}

// ---------------- GEMM: HS = A@W, S = HS@asrc, D = A@wd ----------------
// BM=128, BN=64, full K in smem. 128 threads, each 8 rows x 8 cols via FFMA2
// (rows paired in the packed halves).
template <int K>
__global__ void __launch_bounds__(128, 2)
k_gemm(const float* __restrict__ A, const float* __restrict__ W,
       const float* __restrict__ asrc,
       const float* __restrict__ wd0, const float* __restrict__ wd1,
       float* __restrict__ HS, float* __restrict__ S,
       float* __restrict__ D0, float* __restrict__ D1, int M) {
    extern __shared__ float sm[];
    float* As  = sm;                  // [K][130] transposed, even stride for LDS.64 pairs
    float* Ws  = sm + K * 130;        // [K][64]
    float* asc = Ws + K * 64;         // [64]
    float* wds = asc + 64;            // [2*K]

    const int tid  = threadIdx.x;
    const int row0 = blockIdx.x * 128;
    const int Mloc = M - row0;        // rows valid in this block (may exceed 128)

    // stage A transposed (coalesced global reads along k)
    for (int idx = tid; idx < 128 * K; idx += 128) {
        int r = idx / K, k = idx - r * K;
        As[k * 130 + r] = (r < Mloc) ? A[(size_t)(row0 + r) * K + k] : 0.f;
    }
    for (int idx = tid; idx < K * 64; idx += 128) Ws[idx] = W[idx];
    if (tid < 64) asc[tid] = asrc[tid];
    if (wd0) {
        for (int idx = tid; idx < K; idx += 128) {
            wds[idx]     = wd0[idx];
            wds[K + idx] = wd1[idx];
        }
    }
    __syncthreads();

    const int tr = tid >> 3;   // 0..15 -> rows tr*8 .. tr*8+7
    const int tc = tid & 7;    // 0..7  -> cols tc*8 .. tc*8+7

    unsigned long long acc[4][8];
#pragma unroll
    for (int p = 0; p < 4; p++)
#pragma unroll
        for (int j = 0; j < 8; j++) acc[p][j] = 0ull;

    const float* AsB = As + tr * 8;
    const float* WsB = Ws + tc * 8;

    for (int k = 0; k < K; k++) {
        unsigned long long a0 = *(const unsigned long long*)(AsB + k * 130 + 0);
        unsigned long long a1 = *(const unsigned long long*)(AsB + k * 130 + 2);
        unsigned long long a2 = *(const unsigned long long*)(AsB + k * 130 + 4);
        unsigned long long a3 = *(const unsigned long long*)(AsB + k * 130 + 6);
        float4 b0 = *(const float4*)(WsB + k * 64);
        float4 b1 = *(const float4*)(WsB + k * 64 + 4);
        unsigned long long bd[8];
        bd[0] = pk2(b0.x); bd[1] = pk2(b0.y); bd[2] = pk2(b0.z); bd[3] = pk2(b0.w);
        bd[4] = pk2(b1.x); bd[5] = pk2(b1.y); bd[6] = pk2(b1.z); bd[7] = pk2(b1.w);
#pragma unroll
        for (int j = 0; j < 8; j++) {
            fma2(acc[0][j], a0, bd[j]);
            fma2(acc[1][j], a1, bd[j]);
            fma2(acc[2][j], a2, bd[j]);
            fma2(acc[3][j], a3, bd[j]);
        }
    }

    // epilogue: write HS, compute S = HS @ asrc (reduce over tc, width 8)
    float ar[8];
#pragma unroll
    for (int j = 0; j < 8; j++) ar[j] = asc[tc * 8 + j];

#pragma unroll
    for (int p = 0; p < 4; p++) {
        float lo[8], hi[8];
#pragma unroll
        for (int j = 0; j < 8; j++) upk(acc[p][j], lo[j], hi[j]);
        int rl = tr * 8 + 2 * p;
        int rh = rl + 1;
        float sl = lo[0]*ar[0]+lo[1]*ar[1]+lo[2]*ar[2]+lo[3]*ar[3]+lo[4]*ar[4]+lo[5]*ar[5]+lo[6]*ar[6]+lo[7]*ar[7];
        float sh = hi[0]*ar[0]+hi[1]*ar[1]+hi[2]*ar[2]+hi[3]*ar[3]+hi[4]*ar[4]+hi[5]*ar[5]+hi[6]*ar[6]+hi[7]*ar[7];
#pragma unroll
        for (int off = 4; off; off >>= 1) {
            sl += __shfl_down_sync(0xffffffffu, sl, off, 8);
            sh += __shfl_down_sync(0xffffffffu, sh, off, 8);
        }
        if (rl < Mloc) {
            float* dstl = &HS[(size_t)(row0 + rl) * 64 + tc * 8];
            *(float4*)dstl       = make_float4(lo[0], lo[1], lo[2], lo[3]);
            *(float4*)(dstl + 4) = make_float4(lo[4], lo[5], lo[6], lo[7]);
            if (tc == 0) S[row0 + rl] = sl;
        }
        if (rh < Mloc) {
            float* dsth = &HS[(size_t)(row0 + rh) * 64 + tc * 8];
            *(float4*)dsth       = make_float4(hi[0], hi[1], hi[2], hi[3]);
            *(float4*)(dsth + 4) = make_float4(hi[4], hi[5], hi[6], hi[7]);
            if (tc == 0) S[row0 + rh] = sh;
        }
    }

    // D = A @ wd for both wd vectors (one row per thread)
    if (wd0 && tid < Mloc && tid < 128) {
        float d0 = 0.f, d1 = 0.f;
        for (int k = 0; k < K; k++) {
            float a = As[k * 130 + tid];
            d0 += a * wds[k];
            d1 += a * wds[K + k];
        }
        D0[row0 + tid] = d0;
        D1[row0 + tid] = d1;
    }
}

// ---------------- bucket scatter: both graphs in one launch ----------------
__global__ void k_scatter2(const int* __restrict__ eii, const int* __restrict__ eei) {
    int e = blockIdx.x * blockDim.x + threadIdx.x;
    if (e < E_II) {
        int d = eii[E_II + e];
        int pos = atomicAdd(&g_deg_ii[d], 1);
        if (pos < CAP_II) g_bkt_ii[(size_t)d * CAP_II + pos] = eii[e];
    } else if (e < E_II + E_EI) {
        int e2 = e - E_II;
        int d = eei[E_EI + e2];
        int pos = atomicAdd(&g_deg_ei[d], 1);
        if (pos < CAP_EI) g_bkt_ei[(size_t)d * CAP_EI + pos] = eei[e2];
    }
}

// ---------------- per-graph gather-aggregate (warp-level helper) ----------------
__device__ __forceinline__ void aggr_one(const int* __restrict__ bkt, int deg,
                                         const float* __restrict__ S, float dval,
                                         const float* __restrict__ HS,
                                         int lane, float2* res) {
    float vx = 0.f, vy = 0.f, esum = 0.f;
    for (int base = 0; base < deg; base += 32) {
        int j = base + lane;
        int sidx = 0;
        float e = 0.f;
        if (j < deg) {
            sidx = bkt[j];
            float a = __ldg(&S[sidx]) + dval;
            a = a > 0.f ? a : F_SLOPE * a;
            e = expf(a);
        }
        int cnt = min(32, deg - base);
#pragma unroll 4
        for (int t = 0; t < cnt; t++) {
            float et = __shfl_sync(0xffffffffu, e, t);
            int   st = __shfl_sync(0xffffffffu, sidx, t);
            float2 h = *(const float2*)&HS[st * 64 + lane * 2];
            vx += et * h.x;
            vy += et * h.y;
        }
        esum += e;
    }
#pragma unroll
    for (int off = 16; off; off >>= 1)
        esum += __shfl_xor_sync(0xffffffffu, esum, off);
    if (esum > 0.f) {
        float inv = 1.f / esum;
        res->x += vx * inv;
        res->y += vy * inv;
    }
}

// ---------------- fused aggregation for both graphs + bias + relu -> emb ----------------
__global__ void k_aggr(const float* __restrict__ b_ii, const float* __restrict__ b_ei) {
    int dst = blockIdx.x * (blockDim.x >> 5) + (threadIdx.x >> 5);
    int lane = threadIdx.x & 31;
    if (dst >= N_I) return;

    float2 res = make_float2(0.f, 0.f);
    int deg0 = min(g_deg_ii[dst], CAP_II);
    int deg1 = min(g_deg_ei[dst], CAP_EI);
    aggr_one(&g_bkt_ii[(size_t)dst * CAP_II], deg0, g_s_ii, g_d_ii[dst], g_hs_ii, lane, &res);
    aggr_one(&g_bkt_ei[(size_t)dst * CAP_EI], deg1, g_s_ei, g_d_ei[dst], g_hs_ei, lane, &res);

    int c0 = lane * 2;
    float v0 = 0.5f * (res.x + __ldg(&b_ii[c0])     + __ldg(&b_ei[c0]));
    float v1 = 0.5f * (res.y + __ldg(&b_ii[c0 + 1]) + __ldg(&b_ei[c0 + 1]));
    float2 o;
    o.x = v0 > 0.f ? v0 : 0.f;
    o.y = v1 > 0.f ? v1 : 0.f;
    *(float2*)&g_emb[dst * 64 + c0] = o;
}

// ---------------- gather chosen embeddings + squared norms ----------------
__global__ void k_ce(const int* __restrict__ chosen) {
    int i = blockIdx.x * (blockDim.x >> 5) + (threadIdx.x >> 5);
    int lane = threadIdx.x & 31;
    if (i >= N_CHOSEN) return;
    int n = chosen[i];
    float v0 = g_emb[n * 64 + lane];
    float v1 = g_emb[n * 64 + 32 + lane];
    g_ce[i * 64 + lane]      = v0;
    g_ce[i * 64 + 32 + lane] = v1;
    float sq = v0 * v0 + v1 * v1;
    for (int off = 16; off; off >>= 1) sq += __shfl_down_sync(0xffffffffu, sq, off);
    if (lane == 0) g_sq[i] = sq;
}

// ---------------- tiled nearest neighbor: 8 i's per block share j-tiles ----------------
__global__ void k_nn2() {
    __shared__ float tile[64 * 65];
    __shared__ float sqj[64];
    __shared__ float cei[8 * 64];
    int tid = threadIdx.x;
    int wid = tid >> 5, lane = tid & 31;
    int i = blockIdx.x * 8 + wid;

    cei[wid * 64 + lane]      = g_ce[i * 64 + lane];
    cei[wid * 64 + 32 + lane] = g_ce[i * 64 + 32 + lane];
    float sqi = g_sq[i];
    float best = 3.4e38f;
    int bestj = 0x7fffffff;

    for (int tb = 0; tb < N_CHOSEN; tb += 64) {
        __syncthreads();
        for (int idx = tid; idx < 64 * 64; idx += 256) {
            int j = idx >> 6, k = idx & 63;
            tile[j * 65 + k] = g_ce[(tb + j) * 64 + k];
        }
        if (tid < 64) sqj[tid] = g_sq[tb + tid];
        __syncthreads();

#pragma unroll
        for (int half = 0; half < 2; half++) {
            int jl = lane + half * 32;
            int j = tb + jl;
            if (j == i) continue;
            float dot = 0.f;
#pragma unroll 16
            for (int k = 0; k < 64; k++) dot += cei[wid * 64 + k] * tile[jl * 65 + k];
            float d2 = sqi + sqj[jl] - 2.f * dot;
            d2 = d2 > 0.f ? d2 : 0.f;
            if (d2 < best || (d2 == best && j < bestj)) { best = d2; bestj = j; }
        }
    }
#pragma unroll
    for (int off = 16; off; off >>= 1) {
        float ob = __shfl_down_sync(0xffffffffu, best, off);
        int   oj = __shfl_down_sync(0xffffffffu, bestj, off);
        if (ob < best || (ob == best && oj < bestj)) { best = ob; bestj = oj; }
    }
    if (lane == 0) g_nb[i] = bestj;
}

// ---------------- classifier head + softmax + extra output sections ----------------
__global__ void k_final(const float* __restrict__ linW, const float* __restrict__ linb,
                        const float* __restrict__ rn, const int* __restrict__ labels,
                        const int* __restrict__ chosen,
                        float* __restrict__ out, int probN, int writeExtras) {
    int n = blockIdx.x * (blockDim.x >> 5) + (threadIdx.x >> 5);
    int lane = threadIdx.x & 31;
    if (n >= probN) return;
    float v0, v1;
    if (n < N_I) {
        v0 = g_emb[n * 64 + lane];
        v1 = g_emb[n * 64 + 32 + lane];
    } else {
        int i = n - N_I;
        int nbi = g_nb[i];
        float c0 = g_ce[i * 64 + lane],   c1 = g_ce[i * 64 + 32 + lane];
        float n0 = g_ce[nbi * 64 + lane], n1 = g_ce[nbi * 64 + 32 + lane];
        v0 = c0 + (n0 - c0) * F_INTERP;
        v1 = c1 + (n1 - c1) * F_INTERP;
    }
    float l0 = v0 * __ldg(&linW[lane * 2])     + v1 * __ldg(&linW[(lane + 32) * 2]);
    float l1 = v0 * __ldg(&linW[lane * 2 + 1]) + v1 * __ldg(&linW[(lane + 32) * 2 + 1]);
    for (int off = 16; off; off >>= 1) {
        l0 += __shfl_down_sync(0xffffffffu, l0, off);
        l1 += __shfl_down_sync(0xffffffffu, l1, off);
    }
    if (lane == 0) {
        l0 += __ldg(&linb[0]);
        l1 += __ldg(&linb[1]);
        float m = fmaxf(l0, l1);
        float e0 = expf(l0 - m), e1 = expf(l1 - m);
        float inv = 1.f / (e0 + e1);
        out[n * 2]     = e0 * inv;
        out[n * 2 + 1] = e1 * inv;
        if (writeExtras) {
            int moff = probN * 2;
            out[moff + n]         = (n >= N_I) ? 1.f : 0.f;
            out[moff + probN + n] = (n < N_I) ? (float)labels[n] : 1.f;
            float r;
            if (n < N_I) r = rn[n];
            else {
                int i = n - N_I;
                float rc = rn[chosen[i]];
                r = rc + (rn[chosen[g_nb[i]]] - rc) * F_INTERP;
            }
            out[moff + 2 * probN + n] = r;
        }
    }
}

__global__ void k_mask(const int* __restrict__ idx_train, float* __restrict__ out, int moff) {
    int t = blockIdx.x * blockDim.x + threadIdx.x;
    if (t < N_TRAIN) out[moff + idx_train[t]] = 1.f;
}

// ---------------- launch ----------------
extern "C" void kernel_launch(void* const* d_in, const int* in_sizes, int n_in,
                              void* d_out, int out_size) {
    const float* x_i     = (const float*)d_in[0];
    const float* x_e     = (const float*)d_in[1];
    const float* Wsrc_ii = (const float*)d_in[2];
    const float* Wdst_ii = (const float*)d_in[3];
    const float* asrc_ii = (const float*)d_in[4];
    const float* adst_ii = (const float*)d_in[5];
    const float* b_ii    = (const float*)d_in[6];
    // d_in[7..11]: ie branch — unused downstream in the reference; skipped.
    const float* Wsrc_ei = (const float*)d_in[12];
    const float* Wdst_ei = (const float*)d_in[13];
    const float* asrc_ei = (const float*)d_in[14];
    const float* adst_ei = (const float*)d_in[15];
    const float* b_ei    = (const float*)d_in[16];
    const float* linW    = (const float*)d_in[17];
    const float* linb    = (const float*)d_in[18];
    const float* rn      = (const float*)d_in[19];
    const int*   eii     = (const int*)d_in[20];
    const int*   eei     = (const int*)d_in[22];
    const int*   labels  = (const int*)d_in[23];
    const int*   idxtr   = (const int*)d_in[24];
    const int*   chosen  = (const int*)d_in[25];
    float* out = (float*)d_out;

    void *p_hs_ii, *p_hs_ei, *p_s_ii, *p_d_ii, *p_d_ei, *p_s_ei;
    void *p_wd_ii, *p_wd_ei, *p_deg_ii, *p_deg_ei;
    cudaGetSymbolAddress(&p_hs_ii, g_hs_ii);
    cudaGetSymbolAddress(&p_hs_ei, g_hs_ei);
    cudaGetSymbolAddress(&p_s_ii, g_s_ii);
    cudaGetSymbolAddress(&p_d_ii, g_d_ii);
    cudaGetSymbolAddress(&p_d_ei, g_d_ei);
    cudaGetSymbolAddress(&p_s_ei, g_s_ei);
    cudaGetSymbolAddress(&p_wd_ii, g_wd_ii);
    cudaGetSymbolAddress(&p_wd_ei, g_wd_ei);
    cudaGetSymbolAddress(&p_deg_ii, g_deg_ii);
    cudaGetSymbolAddress(&p_deg_ei, g_deg_ei);

    cudaMemsetAsync(p_deg_ii, 0, (size_t)N_I * sizeof(int));
    cudaMemsetAsync(p_deg_ei, 0, (size_t)N_I * sizeof(int));

    k_wd<<<1, 128>>>(Wdst_ii, adst_ii, Wdst_ei, adst_ei);

    k_scatter2<<<(E_II + E_EI + 255) / 256, 256>>>(eii, eei);

    size_t sm128 = (size_t)(128 * 130 + 128 * 64 + 64 + 2 * 128) * sizeof(float);  // 100608
    size_t sm64  = (size_t)(64 * 130 + 64 * 64 + 64) * sizeof(float);              // 49920
    cudaFuncSetAttribute(k_gemm<128>, cudaFuncAttributeMaxDynamicSharedMemorySize, (int)sm128);
    cudaFuncSetAttribute(k_gemm<64>,  cudaFuncAttributeMaxDynamicSharedMemorySize, (int)sm64);

    k_gemm<128><<<(N_I + 127) / 128, 128, sm128>>>(
        x_i, Wsrc_ii, asrc_ii, (const float*)p_wd_ii, (const float*)p_wd_ei,
        (float*)p_hs_ii, (float*)p_s_ii, (float*)p_d_ii, (float*)p_d_ei, N_I);
    k_gemm<64><<<(N_E + 127) / 128, 128, sm64>>>(
        x_e, Wsrc_ei, asrc_ei, nullptr, nullptr,
        (float*)p_hs_ei, (float*)p_s_ei, nullptr, nullptr, N_E);

    k_aggr<<<(N_I + 7) / 8, 256>>>(b_ii, b_ei);

    k_ce<<<(N_CHOSEN + 7) / 8, 256>>>(chosen);
    k_nn2<<<N_CHOSEN / 8, 256>>>();

    int probN = N_I + N_CHOSEN;
    int writeExtras = (out_size >= probN * 5) ? 1 : 0;
    k_final<<<(probN + 7) / 8, 256>>>(linW, linb, rn, labels, chosen, out, probN, writeExtras);
    if (writeExtras) k_mask<<<(N_TRAIN + 255) / 256, 256>>>(idxtr, out, probN * 2);
}